// round 9
// baseline (speedup 1.0000x reference)
#include <cuda_runtime.h>
#include <cstdint>

// DotProductCostVolume: out[b,d,h,w] = (1/C) * sum_c left[b,c,h,w]*right[b,c,h,w-d], 0 if w<d
// B=4, C=32, H=256, W=512, D=64, fp32.
//
// CTA = (b, h, 128-wide w-tile), 128 threads. R9: 6 CTAs/SM (24 warps) — R7's
// profile showed nothing saturated (issue 45%, fma 34%, L1 79%) at 4 CTAs/SM;
// the binder is latency exposure, so buy warps. Register diet to fit the
// 106-reg cap: per channel, R is consumed in two float4 halves (upper triangle
// j>i uses rv[1..7], lower j<=i uses rv[8..15]) -> live set ~95 regs.
// Everything else is R7 verbatim: 3-stage cp.async ring, one barrier/chunk,
// zfill halo (w<d masking automatic), conflict-free swizzled LDS.128, __stcs.

#define Bn 4
#define Cn 32
#define Hn 256
#define Wn 512
#define Dn 64
#define TW 128           // output w-columns per CTA
#define RW 192           // TW + 64 halo columns of right
#define NT 128           // threads per CTA
#define CH 8             // channels per pipeline chunk
#define NCH (Cn/CH)      // 4 chunks
#define NST 3            // pipeline stages

#define LCH (TW/4)       // 32 float4 chunks per L row
#define RCH (RW/4)       // 48 float4 chunks per R row
#define LST (CH*LCH)     // 256 float4 per L stage
#define RST (CH*RCH)     // 384 float4 per R stage

// 16B-chunk XOR swizzle (row-local chunk index q): conflict-free LDS.128.
__device__ __forceinline__ int swc(int q) { return q ^ ((q >> 3) & 7); }

__device__ __forceinline__ void cp16(uint32_t s, const void* g, bool valid) {
    asm volatile("cp.async.cg.shared.global [%0], [%1], 16, %2;"
                 :: "r"(s), "l"(g), "r"(valid ? 16 : 0));
}
__device__ __forceinline__ void cp_commit() {
    asm volatile("cp.async.commit_group;");
}

__global__ __launch_bounds__(NT, 6)
void cost_volume_kernel(const float* __restrict__ left,
                        const float* __restrict__ right,
                        float* __restrict__ out)
{
    __shared__ float4 Ls4[NST * LST];   // 12 KB
    __shared__ float4 Rs4[NST * RST];   // 18 KB

    const int tile = blockIdx.x;    // 0..3
    const int h    = blockIdx.y;    // 0..255
    const int b    = blockIdx.z;    // 0..3
    const int w0   = tile * TW;
    const int tid  = threadIdx.x;

    const float* lbase = left  + ((long)(b * Cn) * Hn + h) * Wn;
    const float* rbase = right + ((long)(b * Cn) * Hn + h) * Wn;

    const uint32_t lsm = (uint32_t)__cvta_generic_to_shared(Ls4);
    const uint32_t rsm = (uint32_t)__cvta_generic_to_shared(Rs4);

    // Prefetch one 8-channel chunk into stage st.
    auto prefetch = [&](int cc, int st) {
        const int c0 = cc * CH;
        #pragma unroll
        for (int it = 0; it < 2; it++) {       // L: 256 f4 / stage
            int idx = tid + it * NT;
            int ch = idx >> 5;
            int q  = idx & (LCH - 1);
            cp16(lsm + (uint32_t)(st * LST + ch * LCH + swc(q)) * 16,
                 lbase + (long)(c0 + ch) * Hn * Wn + w0 + 4 * q, true);
        }
        #pragma unroll
        for (int it = 0; it < 3; it++) {       // R: 384 f4 / stage
            int idx = tid + it * NT;
            int ch = idx / RCH;
            int q  = idx - ch * RCH;
            int gw = w0 - 64 + 4 * q;          // chunk entirely <0 or >=0
            bool v = (gw >= 0);
            cp16(rsm + (uint32_t)(st * RST + ch * RCH + swc(q)) * 16,
                 rbase + (long)(c0 + ch) * Hn * Wn + (v ? gw : 0), v);
        }
        cp_commit();
    };

    // ---- Per-thread 8w x 8d register tile ----
    const int wg = tid & 15;   // w-group: w0 + 8wg .. +7
    const int dg = tid >> 4;   // d-group: 8dg .. +7

    const int lo0 = swc(2 * wg);
    const int lo1 = swc(2 * wg + 1);
    // R words rv[n] = word (8wg-8dg+56)+n, n in [0,15]; base 4-aligned.
    const int q0  = 2 * (wg - dg) + 14;          // in [0,44]
    const int ro0 = swc(q0 + 0), ro1 = swc(q0 + 1);
    const int ro2 = swc(q0 + 2), ro3 = swc(q0 + 3);

    float acc[8][8];
    #pragma unroll
    for (int i = 0; i < 8; i++)
        #pragma unroll
        for (int j = 0; j < 8; j++)
            acc[i][j] = 0.0f;

    prefetch(0, 0);
    prefetch(1, 1);

    for (int cc = 0; cc < NCH; cc++) {
        const int st = cc % NST;
        if (cc < NCH - 1) asm volatile("cp.async.wait_group 1;");
        else              asm volatile("cp.async.wait_group 0;");
        __syncthreads();   // single barrier per chunk (3-stage ring makes the
                           // pre-overwrite barrier provably redundant)
        if (cc + 2 < NCH) prefetch(cc + 2, (cc + 2) % NST);

        const float4* Lp = Ls4 + st * LST;
        const float4* Rp = Rs4 + st * RST;

        #pragma unroll
        for (int c = 0; c < CH; c++) {
            float4 la = Lp[c * LCH + lo0];
            float4 lb = Lp[c * LCH + lo1];
            float l[8] = { la.x, la.y, la.z, la.w, lb.x, lb.y, lb.z, lb.w };

            // ---- Half 1: rv[0..7] (chunks ro0, ro1) feeds cells j > i ----
            {
                float4 r0 = Rp[c * RCH + ro0];
                float4 r1 = Rp[c * RCH + ro1];
                float rv[8] = { r0.x, r0.y, r0.z, r0.w,
                                r1.x, r1.y, r1.z, r1.w };
                #pragma unroll
                for (int i = 0; i < 8; i++)
                    #pragma unroll
                    for (int j = 0; j < 8; j++)
                        if (j > i)                       // n = 8+i-j in [1,7]
                            acc[i][j] += l[i] * rv[8 + i - j];
            }
            // ---- Half 2: rv[8..15] (chunks ro2, ro3) feeds cells j <= i ----
            {
                float4 r2 = Rp[c * RCH + ro2];
                float4 r3 = Rp[c * RCH + ro3];
                float rv[8] = { r2.x, r2.y, r2.z, r2.w,
                                r3.x, r3.y, r3.z, r3.w };
                #pragma unroll
                for (int i = 0; i < 8; i++)
                    #pragma unroll
                    for (int j = 0; j < 8; j++)
                        if (j <= i)                      // n = 8+i-j in [8,15]
                            acc[i][j] += l[i] * rv[i - j];
            }
        }
    }

    // ---- Epilogue: scale by 1/C, streaming vectorized stores ----
    const float sc = 1.0f / (float)Cn;
    float* ob = out + ((long)(b * Dn) * Hn + h) * Wn + w0 + wg * 8;
    #pragma unroll
    for (int j = 0; j < 8; j++) {
        int d = dg * 8 + j;
        float4 v0 = make_float4(acc[0][j] * sc, acc[1][j] * sc,
                                acc[2][j] * sc, acc[3][j] * sc);
        float4 v1 = make_float4(acc[4][j] * sc, acc[5][j] * sc,
                                acc[6][j] * sc, acc[7][j] * sc);
        float4* p = reinterpret_cast<float4*>(ob + (long)d * Hn * Wn);
        __stcs(p + 0, v0);
        __stcs(p + 1, v1);
    }
}

extern "C" void kernel_launch(void* const* d_in, const int* in_sizes, int n_in,
                              void* d_out, int out_size)
{
    const float* left  = (const float*)d_in[0];
    const float* right = (const float*)d_in[1];
    float* out = (float*)d_out;

    dim3 grid(Wn / TW, Hn, Bn);   // (4, 256, 4) = 4096 CTAs
    cost_volume_kernel<<<grid, NT>>>(left, right, out);
}

// round 10
// speedup vs baseline: 2.7967x; 2.7967x over previous
#include <cuda_runtime.h>
#include <cstdint>

// DotProductCostVolume: out[b,d,h,w] = (1/C) * sum_c left[b,c,h,w]*right[b,c,h,w-d], 0 if w<d
// B=4, C=32, H=256, W=512, D=64, fp32.
//
// R7 config (best: 84.5us): CTA = (b, h, 128-wide w-tile), 128 threads,
// 4 CTAs/SM, 3-stage cp.async ring (8 ch/chunk), one barrier per chunk,
// zfill halo (w<d masking automatic), swizzled conflict-free LDS.128, __stcs.
// R10 change: explicit register double-buffering of the channel loop — the
// next channel's 2 L + 4 R quads are fetched BEFORE the current channel's 64
// FFMAs, hiding the LDS scoreboard wait that left the FMA pipe 66% idle
// (fma=34%). Live regs ~126 <= 128 cap (acc 64 + cur 24 + next 24 + addr).

#define Bn 4
#define Cn 32
#define Hn 256
#define Wn 512
#define Dn 64
#define TW 128           // output w-columns per CTA
#define RW 192           // TW + 64 halo columns of right
#define NT 128           // threads per CTA
#define CH 8             // channels per pipeline chunk
#define NCH (Cn/CH)      // 4 chunks
#define NST 3            // pipeline stages

#define LCH (TW/4)       // 32 float4 chunks per L row
#define RCH (RW/4)       // 48 float4 chunks per R row
#define LST (CH*LCH)     // 256 float4 per L stage
#define RST (CH*RCH)     // 384 float4 per R stage

// 16B-chunk XOR swizzle (row-local chunk index q): conflict-free LDS.128.
__device__ __forceinline__ int swc(int q) { return q ^ ((q >> 3) & 7); }

__device__ __forceinline__ void cp16(uint32_t s, const void* g, bool valid) {
    asm volatile("cp.async.cg.shared.global [%0], [%1], 16, %2;"
                 :: "r"(s), "l"(g), "r"(valid ? 16 : 0));
}
__device__ __forceinline__ void cp_commit() {
    asm volatile("cp.async.commit_group;");
}

__global__ __launch_bounds__(NT, 4)
void cost_volume_kernel(const float* __restrict__ left,
                        const float* __restrict__ right,
                        float* __restrict__ out)
{
    __shared__ float4 Ls4[NST * LST];   // 12 KB
    __shared__ float4 Rs4[NST * RST];   // 18 KB

    const int tile = blockIdx.x;    // 0..3
    const int h    = blockIdx.y;    // 0..255
    const int b    = blockIdx.z;    // 0..3
    const int w0   = tile * TW;
    const int tid  = threadIdx.x;

    const float* lbase = left  + ((long)(b * Cn) * Hn + h) * Wn;
    const float* rbase = right + ((long)(b * Cn) * Hn + h) * Wn;

    const uint32_t lsm = (uint32_t)__cvta_generic_to_shared(Ls4);
    const uint32_t rsm = (uint32_t)__cvta_generic_to_shared(Rs4);

    // Prefetch one 8-channel chunk into stage st.
    auto prefetch = [&](int cc, int st) {
        const int c0 = cc * CH;
        #pragma unroll
        for (int it = 0; it < 2; it++) {       // L: 256 f4 / stage
            int idx = tid + it * NT;
            int ch = idx >> 5;
            int q  = idx & (LCH - 1);
            cp16(lsm + (uint32_t)(st * LST + ch * LCH + swc(q)) * 16,
                 lbase + (long)(c0 + ch) * Hn * Wn + w0 + 4 * q, true);
        }
        #pragma unroll
        for (int it = 0; it < 3; it++) {       // R: 384 f4 / stage
            int idx = tid + it * NT;
            int ch = idx / RCH;
            int q  = idx - ch * RCH;
            int gw = w0 - 64 + 4 * q;          // chunk entirely <0 or >=0
            bool v = (gw >= 0);
            cp16(rsm + (uint32_t)(st * RST + ch * RCH + swc(q)) * 16,
                 rbase + (long)(c0 + ch) * Hn * Wn + (v ? gw : 0), v);
        }
        cp_commit();
    };

    // ---- Per-thread 8w x 8d register tile ----
    const int wg = tid & 15;   // w-group: w0 + 8wg .. +7
    const int dg = tid >> 4;   // d-group: 8dg .. +7

    const int lo0 = swc(2 * wg);
    const int lo1 = swc(2 * wg + 1);
    // R words rv[n] = word (8wg-8dg+56)+n, n in [0,15]; base 4-aligned.
    const int q0  = 2 * (wg - dg) + 14;          // in [0,44]
    const int ro0 = swc(q0 + 0), ro1 = swc(q0 + 1);
    const int ro2 = swc(q0 + 2), ro3 = swc(q0 + 3);

    float acc[8][8];
    #pragma unroll
    for (int i = 0; i < 8; i++)
        #pragma unroll
        for (int j = 0; j < 8; j++)
            acc[i][j] = 0.0f;

    prefetch(0, 0);
    prefetch(1, 1);

    for (int cc = 0; cc < NCH; cc++) {
        const int st = cc % NST;
        if (cc < NCH - 1) asm volatile("cp.async.wait_group 1;");
        else              asm volatile("cp.async.wait_group 0;");
        __syncthreads();   // single barrier per chunk (3-stage ring makes the
                           // pre-overwrite barrier provably redundant)
        if (cc + 2 < NCH) prefetch(cc + 2, (cc + 2) % NST);

        const float4* Lp = Ls4 + st * LST;
        const float4* Rp = Rs4 + st * RST;

        // Register double-buffered channel loop: fetch c+1 before c's FMAs.
        float4 la = Lp[lo0];
        float4 lb = Lp[lo1];
        float4 r0 = Rp[ro0];
        float4 r1 = Rp[ro1];
        float4 r2 = Rp[ro2];
        float4 r3 = Rp[ro3];

        #pragma unroll
        for (int c = 0; c < CH; c++) {
            float4 nla, nlb, nr0, nr1, nr2, nr3;
            if (c + 1 < CH) {
                const float4* Ln = Lp + (c + 1) * LCH;
                const float4* Rn = Rp + (c + 1) * RCH;
                nr0 = Rn[ro0];
                nr1 = Rn[ro1];
                nr2 = Rn[ro2];
                nr3 = Rn[ro3];
                nla = Ln[lo0];
                nlb = Ln[lo1];
            }

            float l[8]   = { la.x, la.y, la.z, la.w, lb.x, lb.y, lb.z, lb.w };
            float rv[16] = { r0.x, r0.y, r0.z, r0.w,  r1.x, r1.y, r1.z, r1.w,
                             r2.x, r2.y, r2.z, r2.w,  r3.x, r3.y, r3.z, r3.w };

            #pragma unroll
            for (int i = 0; i < 8; i++)
                #pragma unroll
                for (int j = 0; j < 8; j++)
                    acc[i][j] += l[i] * rv[8 + i - j];   // n in [1,15]

            if (c + 1 < CH) {
                la = nla; lb = nlb;
                r0 = nr0; r1 = nr1; r2 = nr2; r3 = nr3;
            }
        }
    }

    // ---- Epilogue: scale by 1/C, streaming vectorized stores ----
    const float sc = 1.0f / (float)Cn;
    float* ob = out + ((long)(b * Dn) * Hn + h) * Wn + w0 + wg * 8;
    #pragma unroll
    for (int j = 0; j < 8; j++) {
        int d = dg * 8 + j;
        float4 v0 = make_float4(acc[0][j] * sc, acc[1][j] * sc,
                                acc[2][j] * sc, acc[3][j] * sc);
        float4 v1 = make_float4(acc[4][j] * sc, acc[5][j] * sc,
                                acc[6][j] * sc, acc[7][j] * sc);
        float4* p = reinterpret_cast<float4*>(ob + (long)d * Hn * Wn);
        __stcs(p + 0, v0);
        __stcs(p + 1, v1);
    }
}

extern "C" void kernel_launch(void* const* d_in, const int* in_sizes, int n_in,
                              void* d_out, int out_size)
{
    const float* left  = (const float*)d_in[0];
    const float* right = (const float*)d_in[1];
    float* out = (float*)d_out;

    dim3 grid(Wn / TW, Hn, Bn);   // (4, 256, 4) = 4096 CTAs
    cost_volume_kernel<<<grid, NT>>>(left, right, out);
}